// round 11
// baseline (speedup 1.0000x reference)
#include <cuda_runtime.h>
#include <cuda_bf16.h>

#define T_LEN   32768
#define C_LEN   512
#define B_LEN   8
#define KSZ     12
#define NT      256
#define NW      8
#define WTILE   512               // outputs per warp-tile
#define BTILE   4096              // outputs per tile
#define NBLK    (T_LEN / BTILE)   // 8 tiles per row
#define GX      2                 // blocks per row
#define LOOPN   (NBLK / GX)       // 4 tiles per block, consecutive
#define EPS_F   1e-9f
#define FULLM   0xFFFFFFFFu

__device__ __forceinline__ float snake(float v, float a, float binv) {
    float sn = __sinf(v * a);
    return fmaf(sn * sn, binv, v);
}

// Window element I for quad Q, shift S:
//   wd[I] = snaked input at warp-frame position Q*128 + l*4 + (S-6+I)
template<int S, int Q, int I>
struct Win {
    static __device__ __forceinline__ void get(float (&wd)[16], const float (&v)[4][4],
                                               const float (&vprev)[4], const float (&vnext)[4],
                                               int l) {
        constexpr int t = S - 6 + I;
        constexpr int d = (t >= 0) ? (t >> 2) : (-((-t + 3) >> 2));
        constexpr int e = t - 4 * d;
        if constexpr (d == 0) {
            wd[I] = v[Q][e];
        } else if constexpr (d < 0) {
            float other;
            if constexpr (Q > 0) other = v[Q - 1][e]; else other = vprev[e];
            float val = (l >= 32 + d) ? other : v[Q][e];
            wd[I] = __shfl_sync(FULLM, val, (l + d) & 31);
        } else {
            float other;
            if constexpr (Q < 3) other = v[Q + 1][e]; else other = vnext[e];
            float val = (l < d) ? other : v[Q][e];
            wd[I] = __shfl_sync(FULLM, val, (l + d) & 31);
        }
        Win<S, Q, I + 1>::get(wd, v, vprev, vnext, l);
    }
};
template<int S, int Q>
struct Win<S, Q, 16> {
    static __device__ __forceinline__ void get(float (&)[16], const float (&)[4][4],
                                               const float (&)[4], const float (&)[4], int) {}
};

template<int S, int Q>
__device__ __forceinline__ void quad_out(const float (&v)[4][4], const float (&vprev)[4],
                                         const float (&vnext)[4], const float (&f)[KSZ],
                                         float* __restrict__ orow, int w0, int l, bool trim) {
    float wd[16];
    Win<S, Q, 0>::get(wd, v, vprev, vnext, l);

    float s0 = wd[0] * f[0], s1 = wd[1] * f[0], s2 = wd[2] * f[0], s3 = wd[3] * f[0];
    #pragma unroll
    for (int k = 1; k < KSZ; ++k) {
        s0 = fmaf(wd[0 + k], f[k], s0);
        s1 = fmaf(wd[1 + k], f[k], s1);
        s2 = fmaf(wd[2 + k], f[k], s2);
        s3 = fmaf(wd[3 + k], f[k], s3);
    }
    const int j0 = w0 + Q * 128 + S + l * 4;
    if constexpr (S >= 2 && Q == 3) {
        if (trim) {   // suppress j > T_LEN (would spill into next row)
            if (j0 + 0 <= T_LEN) orow[j0 + 0] = s0;
            if (j0 + 1 <= T_LEN) orow[j0 + 1] = s1;
            if (j0 + 2 <= T_LEN) orow[j0 + 2] = s2;
            if (j0 + 3 <= T_LEN) orow[j0 + 3] = s3;
            return;
        }
    }
    __stcs((float4*)(orow + j0), make_float4(s0, s1, s2, s3));
}

template<int S>
__device__ __forceinline__ void run_all(const float (&v)[4][4], const float (&vprev)[4],
                                        const float (&vnext)[4], const float (&f)[KSZ],
                                        float* __restrict__ orow, int w0, int l, bool trim) {
    quad_out<S, 0>(v, vprev, vnext, f, orow, w0, l, trim);
    quad_out<S, 1>(v, vprev, vnext, f, orow, w0, l, trim);
    quad_out<S, 2>(v, vprev, vnext, f, orow, w0, l, trim);
    quad_out<S, 3>(v, vprev, vnext, f, orow, w0, l, trim);
}

// Front outputs [0, S) of a row, scalar with reflect.
template<int S>
__device__ __forceinline__ void front_fix(const float* __restrict__ xr, const float (&f)[KSZ],
                                          float* __restrict__ orow, float a, float binv) {
    #pragma unroll
    for (int j = 0; j < S; ++j) {
        float acc = 0.0f;
        #pragma unroll
        for (int k = 0; k < KSZ; ++k) {
            int g = j - 6 + k;
            if (g < 0) g = -g;
            acc = fmaf(snake(xr[g], a, binv), f[k], acc);
        }
        orow[j] = acc;
    }
}

__device__ __forceinline__ void snake4(float (&dst)[4], const float4& q, float a, float binv) {
    dst[0] = snake(q.x, a, binv); dst[1] = snake(q.y, a, binv);
    dst[2] = snake(q.z, a, binv); dst[3] = snake(q.w, a, binv);
}

__device__ __forceinline__ void edge_halo(float (&vprev)[4], float (&vnext)[4],
                                          const float haloL[NW][12], const float haloR[NW][8],
                                          const float* __restrict__ xr,
                                          int w0, int wp, int l, float a, float binv) {
    if (l >= 30) {
        if (wp > 0) {
            #pragma unroll
            for (int e = 0; e < 4; ++e) vprev[e] = haloR[wp - 1][(l - 30) * 4 + e];
        } else {
            #pragma unroll
            for (int e = 0; e < 4; ++e) {
                int g = w0 - 8 + (l - 30) * 4 + e;
                if (g < 0) g = -g;
                vprev[e] = snake(xr[g], a, binv);
            }
        }
    }
    if (l < 3) {
        if (wp < NW - 1) {
            #pragma unroll
            for (int e = 0; e < 4; ++e) vnext[e] = haloL[wp + 1][l * 4 + e];
        } else {
            #pragma unroll
            for (int e = 0; e < 4; ++e) {
                int g = w0 + 512 + l * 4 + e;
                if (g >= T_LEN) g = 2 * (T_LEN - 1) - g;
                vnext[e] = snake(xr[g], a, binv);
            }
        }
    }
}

// Loop over LOOPN consecutive tiles with one-tile-ahead LDG prefetch.
template<int S>
__device__ __forceinline__ void row_run(const float* __restrict__ xr,
                                        float* __restrict__ orow,
                                        float a, float binv, const float (&f)[KSZ],
                                        int bx, int wp, int l,
                                        float haloL[NW][12], float haloR[NW][8]) {
    const int tile0 = bx * LOOPN;
    const int wbase = tile0 * BTILE + wp * WTILE;

    const float4* __restrict__ xv = (const float4*)(xr + wbase);
    float4 q0 = __ldcs(&xv[l]);
    float4 q1 = __ldcs(&xv[32 + l]);
    float4 q2 = __ldcs(&xv[64 + l]);
    float4 q3 = __ldcs(&xv[96 + l]);

    #pragma unroll
    for (int t = 0; t < LOOPN; ++t) {
        const int w0 = wbase + t * BTILE;

        // Prefetch next tile before computing this one.
        float4 p0, p1, p2, p3;
        if (t + 1 < LOOPN) {
            const float4* __restrict__ xvn = (const float4*)(xr + w0 + BTILE);
            p0 = __ldcs(&xvn[l]);
            p1 = __ldcs(&xvn[32 + l]);
            p2 = __ldcs(&xvn[64 + l]);
            p3 = __ldcs(&xvn[96 + l]);
        }

        float v[4][4];
        snake4(v[0], q0, a, binv); snake4(v[1], q1, a, binv);
        snake4(v[2], q2, a, binv); snake4(v[3], q3, a, binv);

        __syncthreads();   // prior iteration's halo readers done
        if (l < 3) {
            #pragma unroll
            for (int e = 0; e < 4; ++e) haloL[wp][l * 4 + e] = v[0][e];
        }
        if (l >= 30) {
            #pragma unroll
            for (int e = 0; e < 4; ++e) haloR[wp][(l - 30) * 4 + e] = v[3][e];
        }
        __syncthreads();

        float vprev[4] = {0,0,0,0}, vnext[4] = {0,0,0,0};
        edge_halo(vprev, vnext, haloL, haloR, xr, w0, wp, l, a, binv);

        const bool trim = (tile0 + t == NBLK - 1) && (wp == NW - 1) && (l == 31);
        run_all<S>(v, vprev, vnext, f, orow, w0, l, trim);

        if (t + 1 < LOOPN) { q0 = p0; q1 = p1; q2 = p2; q3 = p3; }
    }
}

__global__ __launch_bounds__(NT)
void snake_aa_kernel(const float* __restrict__ x,
                     const float* __restrict__ alpha,
                     const float* __restrict__ beta,
                     const float* __restrict__ filt,
                     float* __restrict__ out) {
    __shared__ float haloL[NW][12];
    __shared__ float haloR[NW][8];

    const int row = blockIdx.y;
    const int c   = row & (C_LEN - 1);
    const int bx  = blockIdx.x;           // 0..GX-1
    const int tid = threadIdx.x;
    const int wp  = tid >> 5;
    const int l   = tid & 31;

    const float a    = __expf(alpha[c]);
    const float binv = 1.0f / (__expf(beta[c]) + EPS_F);
    const float* __restrict__ xr = x + (size_t)row * T_LEN;
    float* __restrict__ orow = out + (size_t)row * (T_LEN + 1);

    float f[KSZ];
    {
        const float4* fv = (const float4*)filt;
        float4 f0 = __ldg(&fv[0]), f1 = __ldg(&fv[1]), f2 = __ldg(&fv[2]);
        f[0]=f0.x; f[1]=f0.y; f[2]=f0.z;  f[3]=f0.w;
        f[4]=f1.x; f[5]=f1.y; f[6]=f1.z;  f[7]=f1.w;
        f[8]=f2.x; f[9]=f2.y; f[10]=f2.z; f[11]=f2.w;
    }

    const int  s    = (4 - (row & 3)) & 3;
    const bool lastb = (bx == GX - 1);

    switch (s) {
    case 0:
        row_run<0>(xr, orow, a, binv, f, bx, wp, l, haloL, haloR);
        if (lastb && tid == 0) {   // tail output t = T_LEN
            float accv = 0.0f;
            #pragma unroll
            for (int k = 0; k < KSZ; ++k) {
                int g = T_LEN - 6 + k;
                if (g >= T_LEN) g = 2 * (T_LEN - 1) - g;
                accv = fmaf(snake(xr[g], a, binv), f[k], accv);
            }
            orow[T_LEN] = accv;
        }
        break;
    case 1:
        row_run<1>(xr, orow, a, binv, f, bx, wp, l, haloL, haloR);
        if (bx == 0 && tid == 0) front_fix<1>(xr, f, orow, a, binv);
        break;
    case 2:
        row_run<2>(xr, orow, a, binv, f, bx, wp, l, haloL, haloR);
        if (bx == 0 && tid == 0) front_fix<2>(xr, f, orow, a, binv);
        break;
    default:
        row_run<3>(xr, orow, a, binv, f, bx, wp, l, haloL, haloR);
        if (bx == 0 && tid == 0) front_fix<3>(xr, f, orow, a, binv);
        break;
    }
}

extern "C" void kernel_launch(void* const* d_in, const int* in_sizes, int n_in,
                              void* d_out, int out_size) {
    const float* x     = (const float*)d_in[0];
    const float* alpha = (const float*)d_in[1];
    const float* beta  = (const float*)d_in[2];
    const float* filt  = (const float*)d_in[3];
    float* out = (float*)d_out;

    dim3 grid(GX, B_LEN * C_LEN);   // (2, 4096)
    snake_aa_kernel<<<grid, NT>>>(x, alpha, beta, filt, out);
}

// round 12
// speedup vs baseline: 1.1850x; 1.1850x over previous
#include <cuda_runtime.h>
#include <cuda_bf16.h>

#define T_LEN   32768
#define C_LEN   512
#define B_LEN   8
#define KSZ     12
#define NT      256
#define NW      8
#define WTILE   512               // outputs per warp
#define BTILE   4096              // outputs per block
#define NBLK    (T_LEN / BTILE)   // 8
#define EPS_F   1e-9f
#define FULLM   0xFFFFFFFFu

__device__ __forceinline__ float snake(float v, float a, float binv) {
    float sn = __sinf(v * a);
    return fmaf(sn * sn, binv, v);
}

// Window element I for quad Q, shift S:
//   wd[I] = snaked input at warp-frame position Q*128 + l*4 + (S-6+I)
template<int S, int Q, int I>
struct Win {
    static __device__ __forceinline__ void get(float (&wd)[16], const float (&v)[4][4],
                                               const float (&vprev)[4], const float (&vnext)[4],
                                               int l) {
        constexpr int t = S - 6 + I;
        constexpr int d = (t >= 0) ? (t >> 2) : (-((-t + 3) >> 2));
        constexpr int e = t - 4 * d;
        if constexpr (d == 0) {
            wd[I] = v[Q][e];
        } else if constexpr (d < 0) {
            float other;
            if constexpr (Q > 0) other = v[Q - 1][e]; else other = vprev[e];
            float val = (l >= 32 + d) ? other : v[Q][e];
            wd[I] = __shfl_sync(FULLM, val, (l + d) & 31);
        } else {
            float other;
            if constexpr (Q < 3) other = v[Q + 1][e]; else other = vnext[e];
            float val = (l < d) ? other : v[Q][e];
            wd[I] = __shfl_sync(FULLM, val, (l + d) & 31);
        }
        Win<S, Q, I + 1>::get(wd, v, vprev, vnext, l);
    }
};
template<int S, int Q>
struct Win<S, Q, 16> {
    static __device__ __forceinline__ void get(float (&)[16], const float (&)[4][4],
                                               const float (&)[4], const float (&)[4], int) {}
};

template<int S, int Q>
__device__ __forceinline__ void quad_out(const float (&v)[4][4], const float (&vprev)[4],
                                         const float (&vnext)[4], const float (&f)[KSZ],
                                         float* __restrict__ orow, int w0, int l, bool trim) {
    float wd[16];
    Win<S, Q, 0>::get(wd, v, vprev, vnext, l);

    float s0 = wd[0] * f[0], s1 = wd[1] * f[0], s2 = wd[2] * f[0], s3 = wd[3] * f[0];
    #pragma unroll
    for (int k = 1; k < KSZ; ++k) {
        s0 = fmaf(wd[0 + k], f[k], s0);
        s1 = fmaf(wd[1 + k], f[k], s1);
        s2 = fmaf(wd[2 + k], f[k], s2);
        s3 = fmaf(wd[3 + k], f[k], s3);
    }
    const int j0 = w0 + Q * 128 + S + l * 4;
    if constexpr (S >= 2 && Q == 3) {
        if (trim) {   // last lane of last warp of last block: suppress j > T_LEN
            if (j0 + 0 <= T_LEN) orow[j0 + 0] = s0;
            if (j0 + 1 <= T_LEN) orow[j0 + 1] = s1;
            if (j0 + 2 <= T_LEN) orow[j0 + 2] = s2;
            if (j0 + 3 <= T_LEN) orow[j0 + 3] = s3;
            return;
        }
    }
    __stcs((float4*)(orow + j0), make_float4(s0, s1, s2, s3));
}

template<int S>
__device__ __forceinline__ void run_all(const float (&v)[4][4], const float (&vprev)[4],
                                        const float (&vnext)[4], const float (&f)[KSZ],
                                        float* __restrict__ orow, int w0, int l, bool trim) {
    quad_out<S, 0>(v, vprev, vnext, f, orow, w0, l, trim);
    quad_out<S, 1>(v, vprev, vnext, f, orow, w0, l, trim);
    quad_out<S, 2>(v, vprev, vnext, f, orow, w0, l, trim);
    quad_out<S, 3>(v, vprev, vnext, f, orow, w0, l, trim);
}

// Front outputs [0, S) of a row, scalar with reflect.
template<int S>
__device__ __forceinline__ void front_fix(const float* __restrict__ xr, const float (&f)[KSZ],
                                          float* __restrict__ orow, float a, float binv) {
    #pragma unroll
    for (int j = 0; j < S; ++j) {
        float acc = 0.0f;
        #pragma unroll
        for (int k = 0; k < KSZ; ++k) {
            int g = j - 6 + k;
            if (g < 0) g = -g;
            acc = fmaf(snake(xr[g], a, binv), f[k], acc);
        }
        orow[j] = acc;
    }
}

__global__ __launch_bounds__(NT, 6)   // cap regs ~40 -> 48 warps/SM
void snake_aa_kernel(const float* __restrict__ x,
                     const float* __restrict__ alpha,
                     const float* __restrict__ beta,
                     const float* __restrict__ filt,
                     float* __restrict__ out) {
    __shared__ float haloL[NW][12];   // warp wp's first 12 snaked values
    __shared__ float haloR[NW][8];    // warp wp's last 8 snaked values

    const int row = blockIdx.y;
    const int c   = row & (C_LEN - 1);
    const int t0  = blockIdx.x * BTILE;
    const int tid = threadIdx.x;
    const int wp  = tid >> 5;
    const int l   = tid & 31;

    const float a    = __expf(alpha[c]);
    const float binv = 1.0f / (__expf(beta[c]) + EPS_F);
    const float* __restrict__ xr = x + (size_t)row * T_LEN;

    const int w0 = t0 + wp * WTILE;

    // Coalesced loads: quad q covers frame [q*128, q*128+128); lane l takes f4 #l.
    const float4* __restrict__ xv = (const float4*)(xr + w0);
    float4 q0 = __ldcs(&xv[l]);
    float4 q1 = __ldcs(&xv[32 + l]);
    float4 q2 = __ldcs(&xv[64 + l]);
    float4 q3 = __ldcs(&xv[96 + l]);

    float v[4][4];
    v[0][0] = snake(q0.x, a, binv); v[0][1] = snake(q0.y, a, binv);
    v[0][2] = snake(q0.z, a, binv); v[0][3] = snake(q0.w, a, binv);
    v[1][0] = snake(q1.x, a, binv); v[1][1] = snake(q1.y, a, binv);
    v[1][2] = snake(q1.z, a, binv); v[1][3] = snake(q1.w, a, binv);
    v[2][0] = snake(q2.x, a, binv); v[2][1] = snake(q2.y, a, binv);
    v[2][2] = snake(q2.z, a, binv); v[2][3] = snake(q2.w, a, binv);
    v[3][0] = snake(q3.x, a, binv); v[3][1] = snake(q3.y, a, binv);
    v[3][2] = snake(q3.z, a, binv); v[3][3] = snake(q3.w, a, binv);

    // Publish warp-edge values.
    if (l < 3) {
        #pragma unroll
        for (int e = 0; e < 4; ++e) haloL[wp][l * 4 + e] = v[0][e];
    }
    if (l >= 30) {
        #pragma unroll
        for (int e = 0; e < 4; ++e) haloR[wp][(l - 30) * 4 + e] = v[3][e];
    }
    __syncthreads();

    // vprev (lanes 30,31): frame positions -8..-1. vnext (lanes 0..2): 512..523.
    float vprev[4] = {0, 0, 0, 0}, vnext[4] = {0, 0, 0, 0};
    if (l >= 30) {
        if (wp > 0) {
            #pragma unroll
            for (int e = 0; e < 4; ++e) vprev[e] = haloR[wp - 1][(l - 30) * 4 + e];
        } else {
            #pragma unroll
            for (int e = 0; e < 4; ++e) {
                int g = w0 - 8 + (l - 30) * 4 + e;
                if (g < 0) g = -g;
                vprev[e] = snake(xr[g], a, binv);
            }
        }
    }
    if (l < 3) {
        if (wp < NW - 1) {
            #pragma unroll
            for (int e = 0; e < 4; ++e) vnext[e] = haloL[wp + 1][l * 4 + e];
        } else {
            #pragma unroll
            for (int e = 0; e < 4; ++e) {
                int g = w0 + 512 + l * 4 + e;
                if (g >= T_LEN) g = 2 * (T_LEN - 1) - g;
                vnext[e] = snake(xr[g], a, binv);
            }
        }
    }

    // Filter: 3 uniform float4 loads.
    float f[KSZ];
    {
        const float4* fv = (const float4*)filt;
        float4 f0 = __ldg(&fv[0]), f1 = __ldg(&fv[1]), f2 = __ldg(&fv[2]);
        f[0]=f0.x; f[1]=f0.y; f[2]=f0.z;  f[3]=f0.w;
        f[4]=f1.x; f[5]=f1.y; f[6]=f1.z;  f[7]=f1.w;
        f[8]=f2.x; f[9]=f2.y; f[10]=f2.z; f[11]=f2.w;
    }

    float* __restrict__ orow = out + (size_t)row * (T_LEN + 1);
    const int  s    = (4 - (row & 3)) & 3;
    const bool last = (blockIdx.x == NBLK - 1);
    const bool trim = last && (wp == NW - 1) && (l == 31);

    switch (s) {
    case 0:
        run_all<0>(v, vprev, vnext, f, orow, w0, l, trim);
        if (last && tid == 0) {   // tail output t = T_LEN
            float accv = 0.0f;
            #pragma unroll
            for (int k = 0; k < KSZ; ++k) {
                int g = T_LEN - 6 + k;
                if (g >= T_LEN) g = 2 * (T_LEN - 1) - g;
                accv = fmaf(snake(xr[g], a, binv), f[k], accv);
            }
            orow[T_LEN] = accv;
        }
        break;
    case 1:
        run_all<1>(v, vprev, vnext, f, orow, w0, l, trim);
        if (blockIdx.x == 0 && tid == 0) front_fix<1>(xr, f, orow, a, binv);
        break;
    case 2:
        run_all<2>(v, vprev, vnext, f, orow, w0, l, trim);
        if (blockIdx.x == 0 && tid == 0) front_fix<2>(xr, f, orow, a, binv);
        break;
    default:
        run_all<3>(v, vprev, vnext, f, orow, w0, l, trim);
        if (blockIdx.x == 0 && tid == 0) front_fix<3>(xr, f, orow, a, binv);
        break;
    }
}

extern "C" void kernel_launch(void* const* d_in, const int* in_sizes, int n_in,
                              void* d_out, int out_size) {
    const float* x     = (const float*)d_in[0];
    const float* alpha = (const float*)d_in[1];
    const float* beta  = (const float*)d_in[2];
    const float* filt  = (const float*)d_in[3];
    float* out = (float*)d_out;

    dim3 grid(NBLK, B_LEN * C_LEN);   // (8, 4096)
    snake_aa_kernel<<<grid, NT>>>(x, alpha, beta, filt, out);
}